// round 8
// baseline (speedup 1.0000x reference)
#include <cuda_runtime.h>
#include <cuda_bf16.h>
#include <stdint.h>
#include <cstdint>
#include <math.h>

#define BB 16
#define NN 8192
#define CC 128
#define NC (NN*CC)          // 1048576
#define BNC (BB*NC)         // 16777216

// ---------------- scratch (device globals; no dynamic allocation) ----------
__device__ float  g_mean[4][NC];       // 0:hf_shared 1:hf_private 2:lf_shared 3:lf_private
__device__ float  g_G[2][BB][CC*CC];   // Gram partials  (2 MB)
__device__ float  g_n2[2][2][BB][CC];  // [pair][0=x/1=s][b][c] centered sum-of-squares
__device__ int    g_ord[2][NN];        // descending-stable argsort of gt_rank rows 0,1
__device__ int    g_cnt[2];            // count(gt_rank[b] > 0)
__device__ double g_acc[8];            // 0 pearson, 1 sep, 2 cost, 3 recon_hf, 4 recon_lf

// ---------------- helpers ---------------------------------------------------
__device__ __forceinline__ float wredf(float v) {
    #pragma unroll
    for (int o = 16; o; o >>= 1) v += __shfl_down_sync(0xffffffffu, v, o);
    return v;
}

__device__ __forceinline__ void block_add(double v, double* target) {
    __shared__ double sd[8];
    #pragma unroll
    for (int o = 16; o; o >>= 1) v += __shfl_down_sync(0xffffffffu, v, o);
    int lane = threadIdx.x & 31, w = threadIdx.x >> 5;
    if (lane == 0) sd[w] = v;
    __syncthreads();
    if (threadIdx.x == 0) {
        double s = 0;
        int nw = blockDim.x >> 5;
        for (int i = 0; i < nw; i++) s += sd[i];
        atomicAdd(target, s);
    }
}

// PTX wrappers (scalar-reference pattern — matches ptx_helpers.cuh style)
__device__ __forceinline__ void ldsm_x4_t(uint32_t& r0, uint32_t& r1,
                                          uint32_t& r2, uint32_t& r3, uint32_t addr) {
    asm volatile("ldmatrix.sync.aligned.m8n8.x4.trans.shared.b16 {%0,%1,%2,%3}, [%4];"
        : "=r"(r0), "=r"(r1), "=r"(r2), "=r"(r3) : "r"(addr));
}

__device__ __forceinline__ void mma_bf16_16816(float& c0, float& c1, float& c2, float& c3,
                                               uint32_t a0, uint32_t a1, uint32_t a2, uint32_t a3,
                                               uint32_t b0, uint32_t b1) {
    asm volatile(
        "mma.sync.aligned.m16n8k16.row.col.f32.bf16.bf16.f32 "
        "{%0,%1,%2,%3}, {%4,%5,%6,%7}, {%8,%9}, {%0,%1,%2,%3};"
        : "+f"(c0), "+f"(c1), "+f"(c2), "+f"(c3)
        : "r"(a0), "r"(a1), "r"(a2), "r"(a3), "r"(b0), "r"(b1));
}

// ---------------- kernels ---------------------------------------------------

__global__ void k_init() {
    int i = blockIdx.x * 256 + threadIdx.x;
    if (i < 2*BB*CC*CC) ((float*)g_G)[i] = 0.f;
    else {
        int j = i - 2*BB*CC*CC;
        if (j < 2*2*BB*CC) ((float*)g_n2)[j] = 0.f;
    }
    if (i < 8) g_acc[i] = 0.0;
    if (i < 2) g_cnt[i] = 0;
}

// batch-means of the 4 shared/private tensors (float4 vectorized)
__global__ void k_mean(const float* __restrict__ a, const float* __restrict__ b,
                       const float* __restrict__ c, const float* __restrict__ d) {
    int idx = blockIdx.x * 256 + threadIdx.x;       // float4 index 0..NC/4-1
    const float4* src; float4* dst;
    switch (blockIdx.y) {
        case 0:  src = (const float4*)a; dst = (float4*)g_mean[0]; break;
        case 1:  src = (const float4*)b; dst = (float4*)g_mean[1]; break;
        case 2:  src = (const float4*)c; dst = (float4*)g_mean[2]; break;
        default: src = (const float4*)d; dst = (float4*)g_mean[3]; break;
    }
    float4 s = make_float4(0.f, 0.f, 0.f, 0.f);
    #pragma unroll
    for (int bb = 0; bb < BB; bb++) {
        float4 v = src[(size_t)bb * (NC/4) + idx];
        s.x += v.x; s.y += v.y; s.z += v.z; s.w += v.w;
    }
    s.x *= 0.0625f; s.y *= 0.0625f; s.z *= 0.0625f; s.w *= 0.0625f;
    dst[idx] = s;
}

// ---- tensor-core split-K Gram: G[pair][b] += Xc^T * Sc (bf16 mma, fp32 acc)
// SMEM tile: [32 k-rows][128 cols] bf16, 256B rows, 16B-chunk XOR swizzle.
__device__ __forceinline__ uint32_t swz(int row, int cbyte) {
    return (uint32_t)(row * 256 + (cbyte ^ ((row & 7) << 4)));
}

__global__ __launch_bounds__(512, 1)
void k_gemm(const float* __restrict__ hf_s, const float* __restrict__ hf_p,
            const float* __restrict__ lf_s, const float* __restrict__ lf_p) {
    __shared__ __align__(16) unsigned char smem[16384];   // X: [0,8K), S: [8K,16K)
    __shared__ float ssq[2][CC];

    int pair = blockIdx.z, b = blockIdx.y;
    const float* X  = pair ? lf_s : hf_s;
    const float* S  = pair ? lf_p : hf_p;
    const float* mX = pair ? g_mean[2] : g_mean[0];
    const float* mS = pair ? g_mean[3] : g_mean[1];
    const float* Xb = X + (size_t)b * NC;
    const float* Sb = S + (size_t)b * NC;

    int t = threadIdx.x;
    int lane = t & 31, warp = t >> 5;
    int wm = (warp >> 2) * 32;          // warp m-origin (c-dim of X)
    int wn = (warp & 3) * 32;           // warp n-origin (c-dim of S)

    uint32_t sbase = (uint32_t)__cvta_generic_to_shared(smem);
    uint32_t sX = sbase, sS = sbase + 8192;

    // loader mapping: 512 threads cover 32 rows x 128 cols; 8 floats/thread/tensor
    int row = t >> 4;                   // 0..31
    int col = (t & 15) * 8;             // 0..120

    // ldmatrix.x4.trans lane address pieces
    int a_r = ((lane >> 4) & 1) * 8 + (lane & 7);
    int a_c = ((lane >> 3) & 1) * 8;
    int b_r = ((lane >> 3) & 1) * 8 + (lane & 7);
    int b_c = ((lane >> 4) & 1) * 8;

    float acc[2][16];
    #pragma unroll
    for (int i = 0; i < 2; i++)
        #pragma unroll
        for (int j = 0; j < 16; j++) acc[i][j] = 0.f;

    float4 sqx0 = make_float4(0.f,0.f,0.f,0.f), sqx1 = make_float4(0.f,0.f,0.f,0.f);
    float4 sqs0 = make_float4(0.f,0.f,0.f,0.f), sqs1 = make_float4(0.f,0.f,0.f,0.f);

    if (t < 2*CC) ((float*)ssq)[t] = 0.f;

    int kbase = blockIdx.x * 1024;

    // prologue prefetch (stage 0)
    float4 px0, px1, ps0, ps1;
    {
        int gi = (kbase + row) * CC + col;
        px0 = *(const float4*)&Xb[gi];   px1 = *(const float4*)&Xb[gi + 4];
        ps0 = *(const float4*)&Sb[gi];   ps1 = *(const float4*)&Sb[gi + 4];
    }

    for (int st = 0; st < 32; st++) {
        int k0 = kbase + st * 32;
        // ---- convert current stage (regs -> centered -> bf16 -> smem)
        {
            int gi = (k0 + row) * CC + col;
            float4 mx0 = *(const float4*)&mX[gi];
            float4 mx1 = *(const float4*)&mX[gi + 4];
            float4 ms0 = *(const float4*)&mS[gi];
            float4 ms1 = *(const float4*)&mS[gi + 4];
            float4 xv0 = make_float4(px0.x-mx0.x, px0.y-mx0.y, px0.z-mx0.z, px0.w-mx0.w);
            float4 xv1 = make_float4(px1.x-mx1.x, px1.y-mx1.y, px1.z-mx1.z, px1.w-mx1.w);
            float4 sv0 = make_float4(ps0.x-ms0.x, ps0.y-ms0.y, ps0.z-ms0.z, ps0.w-ms0.w);
            float4 sv1 = make_float4(ps1.x-ms1.x, ps1.y-ms1.y, ps1.z-ms1.z, ps1.w-ms1.w);
            sqx0.x += xv0.x*xv0.x; sqx0.y += xv0.y*xv0.y; sqx0.z += xv0.z*xv0.z; sqx0.w += xv0.w*xv0.w;
            sqx1.x += xv1.x*xv1.x; sqx1.y += xv1.y*xv1.y; sqx1.z += xv1.z*xv1.z; sqx1.w += xv1.w*xv1.w;
            sqs0.x += sv0.x*sv0.x; sqs0.y += sv0.y*sv0.y; sqs0.z += sv0.z*sv0.z; sqs0.w += sv0.w*sv0.w;
            sqs1.x += sv1.x*sv1.x; sqs1.y += sv1.y*sv1.y; sqs1.z += sv1.z*sv1.z; sqs1.w += sv1.w*sv1.w;
            __nv_bfloat162 xa = __floats2bfloat162_rn(xv0.x, xv0.y);
            __nv_bfloat162 xb2 = __floats2bfloat162_rn(xv0.z, xv0.w);
            __nv_bfloat162 xc = __floats2bfloat162_rn(xv1.x, xv1.y);
            __nv_bfloat162 xd = __floats2bfloat162_rn(xv1.z, xv1.w);
            __nv_bfloat162 sa = __floats2bfloat162_rn(sv0.x, sv0.y);
            __nv_bfloat162 sb2 = __floats2bfloat162_rn(sv0.z, sv0.w);
            __nv_bfloat162 sc = __floats2bfloat162_rn(sv1.x, sv1.y);
            __nv_bfloat162 sd2 = __floats2bfloat162_rn(sv1.z, sv1.w);
            uint32_t ad = swz(row, col * 2);
            *(uint4*)(smem + ad) = make_uint4(*(uint32_t*)&xa, *(uint32_t*)&xb2,
                                              *(uint32_t*)&xc, *(uint32_t*)&xd);
            *(uint4*)(smem + 8192 + ad) = make_uint4(*(uint32_t*)&sa, *(uint32_t*)&sb2,
                                                     *(uint32_t*)&sc, *(uint32_t*)&sd2);
        }
        __syncthreads();

        // ---- prefetch next stage (LDGs issued before MMAs; consumed next iter)
        if (st + 1 < 32) {
            int gi = (k0 + 32 + row) * CC + col;
            px0 = *(const float4*)&Xb[gi];   px1 = *(const float4*)&Xb[gi + 4];
            ps0 = *(const float4*)&Sb[gi];   ps1 = *(const float4*)&Sb[gi + 4];
        }

        // ---- MMAs over current smem tile
        #pragma unroll
        for (int kk = 0; kk < 32; kk += 16) {
            uint32_t A0[4], A1[4], B0[4], B1[4];
            int ra = kk + a_r;
            ldsm_x4_t(A0[0], A0[1], A0[2], A0[3], sX + swz(ra, (wm      + a_c) * 2));
            ldsm_x4_t(A1[0], A1[1], A1[2], A1[3], sX + swz(ra, (wm + 16 + a_c) * 2));
            int rb = kk + b_r;
            ldsm_x4_t(B0[0], B0[1], B0[2], B0[3], sS + swz(rb, (wn      + b_c) * 2));
            ldsm_x4_t(B1[0], B1[1], B1[2], B1[3], sS + swz(rb, (wn + 16 + b_c) * 2));
            #pragma unroll
            for (int i = 0; i < 2; i++) {
                uint32_t* Ai = (i == 0) ? A0 : A1;
                mma_bf16_16816(acc[i][0],  acc[i][1],  acc[i][2],  acc[i][3],
                               Ai[0], Ai[1], Ai[2], Ai[3], B0[0], B0[1]);
                mma_bf16_16816(acc[i][4],  acc[i][5],  acc[i][6],  acc[i][7],
                               Ai[0], Ai[1], Ai[2], Ai[3], B0[2], B0[3]);
                mma_bf16_16816(acc[i][8],  acc[i][9],  acc[i][10], acc[i][11],
                               Ai[0], Ai[1], Ai[2], Ai[3], B1[0], B1[1]);
                mma_bf16_16816(acc[i][12], acc[i][13], acc[i][14], acc[i][15],
                               Ai[0], Ai[1], Ai[2], Ai[3], B1[2], B1[3]);
            }
        }
        __syncthreads();
    }

    // epilogue: merge split-K partials
    float* Gp = g_G[pair][b];
    int grp = lane >> 2, tg = lane & 3;
    #pragma unroll
    for (int i = 0; i < 2; i++) {
        #pragma unroll
        for (int j2 = 0; j2 < 4; j2++) {
            int m = wm + 16 * i + grp;
            int d = wn + 8 * j2 + tg * 2;
            atomicAdd(&Gp[m * CC + d],           acc[i][j2 * 4 + 0]);
            atomicAdd(&Gp[m * CC + d + 1],       acc[i][j2 * 4 + 1]);
            atomicAdd(&Gp[(m + 8) * CC + d],     acc[i][j2 * 4 + 2]);
            atomicAdd(&Gp[(m + 8) * CC + d + 1], acc[i][j2 * 4 + 3]);
        }
    }
    // column sum-of-squares: reduce through smem, then 1 global atomic per col
    atomicAdd(&ssq[0][col],     sqx0.x); atomicAdd(&ssq[0][col + 1], sqx0.y);
    atomicAdd(&ssq[0][col + 2], sqx0.z); atomicAdd(&ssq[0][col + 3], sqx0.w);
    atomicAdd(&ssq[0][col + 4], sqx1.x); atomicAdd(&ssq[0][col + 5], sqx1.y);
    atomicAdd(&ssq[0][col + 6], sqx1.z); atomicAdd(&ssq[0][col + 7], sqx1.w);
    atomicAdd(&ssq[1][col],     sqs0.x); atomicAdd(&ssq[1][col + 1], sqs0.y);
    atomicAdd(&ssq[1][col + 2], sqs0.z); atomicAdd(&ssq[1][col + 3], sqs0.w);
    atomicAdd(&ssq[1][col + 4], sqs1.x); atomicAdd(&ssq[1][col + 5], sqs1.y);
    atomicAdd(&ssq[1][col + 6], sqs1.z); atomicAdd(&ssq[1][col + 7], sqs1.w);
    __syncthreads();
    if (t < CC)            atomicAdd(&g_n2[pair][0][b][t],      ssq[0][t]);
    else if (t < 2*CC)     atomicAdd(&g_n2[pair][1][b][t - CC], ssq[1][t - CC]);
}

// reconstruction MSE sums (float4 vectorized, both pairs)
__global__ void k_recon(const float* __restrict__ r_hf, const float* __restrict__ hf,
                        const float* __restrict__ r_lf, const float* __restrict__ lf) {
    int pair = blockIdx.y;
    const float4* r = (const float4*)(pair ? r_lf : r_hf);
    const float4* o = (const float4*)(pair ? lf   : hf);
    float local = 0.f;
    int stride = gridDim.x * blockDim.x;
    for (int i = blockIdx.x * blockDim.x + threadIdx.x; i < BNC/4; i += stride) {
        float4 a = r[i], bq = o[i];
        float dx = a.x - bq.x, dy = a.y - bq.y, dz = a.z - bq.z, dw = a.w - bq.w;
        local += dx*dx + dy*dy + dz*dz + dw*dw;
    }
    block_add((double)local, &g_acc[3 + pair]);
}

// stable descending argsort rank (count-based) + positives count
__global__ void k_rank(const float* __restrict__ gt) {
    __shared__ float row[NN];
    int batch = blockIdx.y;
    const float* gr = gt + batch * NN;
    for (int j = threadIdx.x; j < NN; j += 128) row[j] = gr[j];
    __syncthreads();

    int i = blockIdx.x * 128 + threadIdx.x;
    float xi = row[i];
    int cgt = 0, ceq = 0;
    for (int j = 0; j < NN; j += 4) {
        float4 v = *(const float4*)&row[j];
        cgt += (v.x > xi) + (v.y > xi) + (v.z > xi) + (v.w > xi);
        ceq += (v.x == xi && j     < i);
        ceq += (v.y == xi && j + 1 < i);
        ceq += (v.z == xi && j + 2 < i);
        ceq += (v.w == xi && j + 3 < i);
    }
    g_ord[batch][cgt + ceq] = i;

    int pos = (xi > 0.f) ? 1 : 0;
    #pragma unroll
    for (int o = 16; o; o >>= 1) pos += __shfl_down_sync(0xffffffffu, pos, o);
    __shared__ int ws[4];
    if ((threadIdx.x & 31) == 0) ws[threadIdx.x >> 5] = pos;
    __syncthreads();
    if (threadIdx.x == 0) atomicAdd(&g_cnt[batch], ws[0] + ws[1] + ws[2] + ws[3]);
}

// masked cosine-embedding sum over sorted pairs (one warp per sorted position)
__global__ void k_sepcos(const float* __restrict__ sep) {
    int w = threadIdx.x >> 5, lane = threadIdx.x & 31;
    int p = blockIdx.x * 8 + w;
    int i0 = g_ord[0][p], i1 = g_ord[1][p];
    const float4* r0 = (const float4*)(sep + (size_t)i0 * CC);
    const float4* r1 = (const float4*)(sep + (size_t)NC + (size_t)i1 * CC);
    float4 a = r0[lane], b = r1[lane];
    float dot = a.x*b.x + a.y*b.y + a.z*b.z + a.w*b.w;
    float nx  = a.x*a.x + a.y*a.y + a.z*a.z + a.w*a.w;
    float ny  = b.x*b.x + b.y*b.y + b.z*b.z + b.w*b.w;
    dot = wredf(dot); nx = wredf(nx); ny = wredf(ny);

    __shared__ double part[8];
    if (lane == 0) {
        int s0 = g_cnt[0]; if (s0 == 0) s0 = NN;
        int s1 = g_cnt[1]; if (s1 == 0) s1 = NN;
        int index = min(s0, s1);
        float cs = dot / (fmaxf(sqrtf(nx), 1e-8f) * fmaxf(sqrtf(ny), 1e-8f));
        part[w] = (p < index) ? (double)(1.f - cs) : 0.0;
    }
    __syncthreads();
    if (threadIdx.x == 0) {
        double s = 0;
        #pragma unroll
        for (int k = 0; k < 8; k++) s += part[k];
        atomicAdd(&g_acc[1], s);
    }
}

// pearson over first 16 rows of flattened [B*N, C]
__global__ void k_pear(const float* __restrict__ x, const float* __restrict__ y) {
    int w = threadIdx.x >> 5, lane = threadIdx.x & 31;
    const float4* xr = (const float4*)(x + w * CC);
    const float4* yr = (const float4*)(y + w * CC);
    float4 a = xr[lane], b = yr[lane];
    float sx  = a.x + a.y + a.z + a.w;
    float sy  = b.x + b.y + b.z + b.w;
    float sxx = a.x*a.x + a.y*a.y + a.z*a.z + a.w*a.w;
    float syy = b.x*b.x + b.y*b.y + b.z*b.z + b.w*b.w;
    float sxy = a.x*b.x + a.y*b.y + a.z*b.z + a.w*b.w;
    sx = wredf(sx); sy = wredf(sy); sxx = wredf(sxx); syy = wredf(syy); sxy = wredf(sxy);
    if (lane == 0) {
        double n = 128.0;
        double num = (double)sxy - (double)sx * (double)sy / n;
        double d2  = ((double)sxx - (double)sx * (double)sx / n) *
                     ((double)syy - (double)sy * (double)sy / n);
        double den = sqrt(d2);
        double r   = (den == 0.0) ? 0.0 : num / den;
        atomicAdd(&g_acc[0], 1.0 - r);
    }
}

// sum of squared normalized correlations over both pairs
__global__ void k_cost() {
    int idx  = blockIdx.x * 256 + threadIdx.x;
    int pair = idx >> 18;
    int rem  = idx & (BB*CC*CC - 1);
    int b    = rem >> 14;
    int cd   = rem & (CC*CC - 1);
    int c    = cd >> 7;
    int d    = cd & (CC - 1);
    float g  = g_G[pair][b][cd];
    float nx = fmaxf(sqrtf(g_n2[pair][0][b][c]), 1e-12f);
    float ns = fmaxf(sqrtf(g_n2[pair][1][b][d]), 1e-12f);
    float v  = g / (nx * ns);
    block_add((double)(v * v), &g_acc[2]);
}

__global__ void k_final(float* __restrict__ out) {
    double sim   = g_acc[0] / 16.0;
    double cost  = g_acc[2] / (double)(BB * CC * CC);
    double recon = (g_acc[3] + g_acc[4]) / (double)BNC;
    int s0 = g_cnt[0]; if (s0 == 0) s0 = NN;
    int s1 = g_cnt[1]; if (s1 == 0) s1 = NN;
    int index = min(s0, s1);
    double gnn = g_acc[1] / (double)index;
    out[0] = (float)(2.0 * sim + 1.0 * cost + 0.05 * recon + gnn);
}

// ---------------- launch ----------------------------------------------------
extern "C" void kernel_launch(void* const* d_in, const int* in_sizes, int n_in,
                              void* d_out, int out_size) {
    const float* hf_f = (const float*)d_in[0];
    const float* lf_f = (const float*)d_in[1];
    const float* hf_s = (const float*)d_in[2];
    const float* lf_s = (const float*)d_in[3];
    const float* hf_p = (const float*)d_in[4];
    const float* lf_p = (const float*)d_in[5];
    const float* r_hf = (const float*)d_in[6];
    const float* r_lf = (const float*)d_in[7];
    const float* sep  = (const float*)d_in[8];
    /* d_in[9] = noi_node: contributes exactly zero (diff_loss on batch-of-1) */
    const float* gt   = (const float*)d_in[10];
    float* out = (float*)d_out;

    k_init  <<<2080, 256>>>();
    k_mean  <<<dim3(NC/4/256, 4), 256>>>(hf_s, hf_p, lf_s, lf_p);
    k_rank  <<<dim3(64, 2), 128>>>(gt);
    k_recon <<<dim3(1024, 2), 256>>>(r_hf, hf_f, r_lf, lf_f);
    k_gemm  <<<dim3(8, 16, 2), 512>>>(hf_s, hf_p, lf_s, lf_p);
    k_sepcos<<<1024, 256>>>(sep);
    k_pear  <<<1, 512>>>(hf_s, lf_s);
    k_cost  <<<2048, 256>>>();
    k_final <<<1, 1>>>(out);
}

// round 9
// speedup vs baseline: 1.0124x; 1.0124x over previous
#include <cuda_runtime.h>
#include <cuda_bf16.h>
#include <stdint.h>
#include <cstdint>
#include <math.h>

#define BB 16
#define NN 8192
#define CC 128
#define NC (NN*CC)          // 1048576
#define BNC (BB*NC)         // 16777216

// ---------------- scratch (device globals; no dynamic allocation) ----------
__device__ float  g_mean[4][NC];       // 0:hf_shared 1:hf_private 2:lf_shared 3:lf_private
__device__ float  g_G[2][BB][CC*CC];   // Gram partials  (2 MB)
__device__ float  g_n2[2][2][BB][CC];  // [pair][0=x/1=s][b][c] centered sum-of-squares
__device__ int    g_ord[2][NN];        // descending-stable argsort of gt_rank rows 0,1
__device__ int    g_cnt[2];            // count(gt_rank[b] > 0)
__device__ double g_acc[8];            // 0 pearson, 1 sep, 2 cost, 3 recon_hf, 4 recon_lf

// ---------------- helpers ---------------------------------------------------
__device__ __forceinline__ float wredf(float v) {
    #pragma unroll
    for (int o = 16; o; o >>= 1) v += __shfl_down_sync(0xffffffffu, v, o);
    return v;
}

__device__ __forceinline__ void block_add(double v, double* target) {
    __shared__ double sd[8];
    #pragma unroll
    for (int o = 16; o; o >>= 1) v += __shfl_down_sync(0xffffffffu, v, o);
    int lane = threadIdx.x & 31, w = threadIdx.x >> 5;
    if (lane == 0) sd[w] = v;
    __syncthreads();
    if (threadIdx.x == 0) {
        double s = 0;
        int nw = blockDim.x >> 5;
        for (int i = 0; i < nw; i++) s += sd[i];
        atomicAdd(target, s);
    }
}

// PTX wrappers (scalar-reference pattern — matches ptx_helpers.cuh style)
__device__ __forceinline__ void ldsm_x4_t(uint32_t& r0, uint32_t& r1,
                                          uint32_t& r2, uint32_t& r3, uint32_t addr) {
    asm volatile("ldmatrix.sync.aligned.m8n8.x4.trans.shared.b16 {%0,%1,%2,%3}, [%4];"
        : "=r"(r0), "=r"(r1), "=r"(r2), "=r"(r3) : "r"(addr));
}

__device__ __forceinline__ void mma_bf16_16816(float& c0, float& c1, float& c2, float& c3,
                                               uint32_t a0, uint32_t a1, uint32_t a2, uint32_t a3,
                                               uint32_t b0, uint32_t b1) {
    asm volatile(
        "mma.sync.aligned.m16n8k16.row.col.f32.bf16.bf16.f32 "
        "{%0,%1,%2,%3}, {%4,%5,%6,%7}, {%8,%9}, {%0,%1,%2,%3};"
        : "+f"(c0), "+f"(c1), "+f"(c2), "+f"(c3)
        : "r"(a0), "r"(a1), "r"(a2), "r"(a3), "r"(b0), "r"(b1));
}

// ---------------- kernels ---------------------------------------------------

__global__ void k_init() {
    int i = blockIdx.x * 256 + threadIdx.x;
    if (i < 2*BB*CC*CC) ((float*)g_G)[i] = 0.f;
    else {
        int j = i - 2*BB*CC*CC;
        if (j < 2*2*BB*CC) ((float*)g_n2)[j] = 0.f;
    }
    if (i < 8) g_acc[i] = 0.0;
    if (i < 2) g_cnt[i] = 0;
}

// batch-means of the 4 shared/private tensors (float4 vectorized)
__global__ void k_mean(const float* __restrict__ a, const float* __restrict__ b,
                       const float* __restrict__ c, const float* __restrict__ d) {
    int idx = blockIdx.x * 256 + threadIdx.x;       // float4 index 0..NC/4-1
    const float4* src; float4* dst;
    switch (blockIdx.y) {
        case 0:  src = (const float4*)a; dst = (float4*)g_mean[0]; break;
        case 1:  src = (const float4*)b; dst = (float4*)g_mean[1]; break;
        case 2:  src = (const float4*)c; dst = (float4*)g_mean[2]; break;
        default: src = (const float4*)d; dst = (float4*)g_mean[3]; break;
    }
    float4 s = make_float4(0.f, 0.f, 0.f, 0.f);
    #pragma unroll
    for (int bb = 0; bb < BB; bb++) {
        float4 v = src[(size_t)bb * (NC/4) + idx];
        s.x += v.x; s.y += v.y; s.z += v.z; s.w += v.w;
    }
    s.x *= 0.0625f; s.y *= 0.0625f; s.z *= 0.0625f; s.w *= 0.0625f;
    dst[idx] = s;
}

// ---- tensor-core split-K Gram: G[pair][b] += Xc^T * Sc (bf16 mma, fp32 acc)
// Double-buffered SMEM tiles: [32 k-rows][128 cols] bf16 per tensor per buffer.
// 256B rows, 16B-chunk XOR swizzle.
__device__ __forceinline__ uint32_t swz(int row, int cbyte) {
    return (uint32_t)(row * 256 + (cbyte ^ ((row & 7) << 4)));
}

__global__ __launch_bounds__(512, 1)
void k_gemm(const float* __restrict__ hf_s, const float* __restrict__ hf_p,
            const float* __restrict__ lf_s, const float* __restrict__ lf_p) {
    // buf0: X @0, S @8192 ; buf1: X @16384, S @24576
    __shared__ __align__(16) unsigned char smem[32768];
    __shared__ float ssq[2][CC];

    int pair = blockIdx.z, b = blockIdx.y;
    const float* X  = pair ? lf_s : hf_s;
    const float* S  = pair ? lf_p : hf_p;
    const float* mX = pair ? g_mean[2] : g_mean[0];
    const float* mS = pair ? g_mean[3] : g_mean[1];
    const float* Xb = X + (size_t)b * NC;
    const float* Sb = S + (size_t)b * NC;

    int t = threadIdx.x;
    int lane = t & 31, warp = t >> 5;
    int wm = (warp >> 2) * 32;          // warp m-origin (c-dim of X)
    int wn = (warp & 3) * 32;           // warp n-origin (c-dim of S)

    uint32_t sbase = (uint32_t)__cvta_generic_to_shared(smem);

    // loader mapping: 512 threads cover 32 rows x 128 cols; 8 floats/thread/tensor
    int row = t >> 4;                   // 0..31
    int col = (t & 15) * 8;             // 0..120

    // ldmatrix.x4.trans lane address pieces
    int a_r = ((lane >> 4) & 1) * 8 + (lane & 7);
    int a_c = ((lane >> 3) & 1) * 8;
    int b_r = ((lane >> 3) & 1) * 8 + (lane & 7);
    int b_c = ((lane >> 4) & 1) * 8;

    float acc[2][16];
    #pragma unroll
    for (int i = 0; i < 2; i++)
        #pragma unroll
        for (int j = 0; j < 16; j++) acc[i][j] = 0.f;

    float4 sqx0 = make_float4(0.f,0.f,0.f,0.f), sqx1 = make_float4(0.f,0.f,0.f,0.f);
    float4 sqs0 = make_float4(0.f,0.f,0.f,0.f), sqs1 = make_float4(0.f,0.f,0.f,0.f);

    if (t < 2*CC) ((float*)ssq)[t] = 0.f;

    int kbase = blockIdx.x * 1024;
    uint32_t ad = swz(row, col * 2);

    // convert lambda-equivalent: center, accumulate squares, pack bf16, store
    #define CONVERT_STORE(BUFOFF, PX0, PX1, PS0, PS1, MX0, MX1, MS0, MS1)             \
    {                                                                                  \
        float4 xv0 = make_float4(PX0.x-MX0.x, PX0.y-MX0.y, PX0.z-MX0.z, PX0.w-MX0.w);  \
        float4 xv1 = make_float4(PX1.x-MX1.x, PX1.y-MX1.y, PX1.z-MX1.z, PX1.w-MX1.w);  \
        float4 sv0 = make_float4(PS0.x-MS0.x, PS0.y-MS0.y, PS0.z-MS0.z, PS0.w-MS0.w);  \
        float4 sv1 = make_float4(PS1.x-MS1.x, PS1.y-MS1.y, PS1.z-MS1.z, PS1.w-MS1.w);  \
        sqx0.x += xv0.x*xv0.x; sqx0.y += xv0.y*xv0.y; sqx0.z += xv0.z*xv0.z; sqx0.w += xv0.w*xv0.w; \
        sqx1.x += xv1.x*xv1.x; sqx1.y += xv1.y*xv1.y; sqx1.z += xv1.z*xv1.z; sqx1.w += xv1.w*xv1.w; \
        sqs0.x += sv0.x*sv0.x; sqs0.y += sv0.y*sv0.y; sqs0.z += sv0.z*sv0.z; sqs0.w += sv0.w*sv0.w; \
        sqs1.x += sv1.x*sv1.x; sqs1.y += sv1.y*sv1.y; sqs1.z += sv1.z*sv1.z; sqs1.w += sv1.w*sv1.w; \
        __nv_bfloat162 xa = __floats2bfloat162_rn(xv0.x, xv0.y);                       \
        __nv_bfloat162 xbq = __floats2bfloat162_rn(xv0.z, xv0.w);                      \
        __nv_bfloat162 xc = __floats2bfloat162_rn(xv1.x, xv1.y);                       \
        __nv_bfloat162 xd = __floats2bfloat162_rn(xv1.z, xv1.w);                       \
        __nv_bfloat162 sa = __floats2bfloat162_rn(sv0.x, sv0.y);                       \
        __nv_bfloat162 sbq = __floats2bfloat162_rn(sv0.z, sv0.w);                      \
        __nv_bfloat162 sc = __floats2bfloat162_rn(sv1.x, sv1.y);                       \
        __nv_bfloat162 sd2 = __floats2bfloat162_rn(sv1.z, sv1.w);                      \
        *(uint4*)(smem + (BUFOFF) + ad) = make_uint4(*(uint32_t*)&xa, *(uint32_t*)&xbq,\
                                                     *(uint32_t*)&xc, *(uint32_t*)&xd);\
        *(uint4*)(smem + (BUFOFF) + 8192 + ad) = make_uint4(*(uint32_t*)&sa, *(uint32_t*)&sbq, \
                                                            *(uint32_t*)&sc, *(uint32_t*)&sd2); \
    }

    // prologue: stage 0 -> buf0
    {
        int gi = (kbase + row) * CC + col;
        float4 px0 = *(const float4*)&Xb[gi];   float4 px1 = *(const float4*)&Xb[gi + 4];
        float4 ps0 = *(const float4*)&Sb[gi];   float4 ps1 = *(const float4*)&Sb[gi + 4];
        float4 mx0 = *(const float4*)&mX[gi];   float4 mx1 = *(const float4*)&mX[gi + 4];
        float4 ms0 = *(const float4*)&mS[gi];   float4 ms1 = *(const float4*)&mS[gi + 4];
        CONVERT_STORE(0, px0, px1, ps0, ps1, mx0, mx1, ms0, ms1);
    }
    __syncthreads();

    for (int st = 0; st < 32; st++) {
        int bufoff  = (st & 1) ? 16384 : 0;
        int nbufoff = (st & 1) ? 0 : 16384;

        // ---- prefetch stage st+1 (data + means) — issued before the MMAs
        float4 px0, px1, ps0, ps1, mx0, mx1, ms0, ms1;
        bool more = (st + 1 < 32);
        if (more) {
            int gi = (kbase + (st + 1) * 32 + row) * CC + col;
            px0 = *(const float4*)&Xb[gi];   px1 = *(const float4*)&Xb[gi + 4];
            ps0 = *(const float4*)&Sb[gi];   ps1 = *(const float4*)&Sb[gi + 4];
            mx0 = *(const float4*)&mX[gi];   mx1 = *(const float4*)&mX[gi + 4];
            ms0 = *(const float4*)&mS[gi];   ms1 = *(const float4*)&mS[gi + 4];
        }

        // ---- MMAs over current buffer
        uint32_t sX = sbase + bufoff, sS = sX + 8192;
        #pragma unroll
        for (int kk = 0; kk < 32; kk += 16) {
            uint32_t A0[4], A1[4], B0[4], B1[4];
            int ra = kk + a_r;
            ldsm_x4_t(A0[0], A0[1], A0[2], A0[3], sX + swz(ra, (wm      + a_c) * 2));
            ldsm_x4_t(A1[0], A1[1], A1[2], A1[3], sX + swz(ra, (wm + 16 + a_c) * 2));
            int rb = kk + b_r;
            ldsm_x4_t(B0[0], B0[1], B0[2], B0[3], sS + swz(rb, (wn      + b_c) * 2));
            ldsm_x4_t(B1[0], B1[1], B1[2], B1[3], sS + swz(rb, (wn + 16 + b_c) * 2));
            #pragma unroll
            for (int i = 0; i < 2; i++) {
                uint32_t* Ai = (i == 0) ? A0 : A1;
                mma_bf16_16816(acc[i][0],  acc[i][1],  acc[i][2],  acc[i][3],
                               Ai[0], Ai[1], Ai[2], Ai[3], B0[0], B0[1]);
                mma_bf16_16816(acc[i][4],  acc[i][5],  acc[i][6],  acc[i][7],
                               Ai[0], Ai[1], Ai[2], Ai[3], B0[2], B0[3]);
                mma_bf16_16816(acc[i][8],  acc[i][9],  acc[i][10], acc[i][11],
                               Ai[0], Ai[1], Ai[2], Ai[3], B1[0], B1[1]);
                mma_bf16_16816(acc[i][12], acc[i][13], acc[i][14], acc[i][15],
                               Ai[0], Ai[1], Ai[2], Ai[3], B1[2], B1[3]);
            }
        }

        // ---- convert stage st+1 into the other buffer (no readers until sync)
        if (more) {
            CONVERT_STORE(nbufoff, px0, px1, ps0, ps1, mx0, mx1, ms0, ms1);
        }
        __syncthreads();
    }
    #undef CONVERT_STORE

    // epilogue: merge split-K partials
    float* Gp = g_G[pair][b];
    int grp = lane >> 2, tg = lane & 3;
    #pragma unroll
    for (int i = 0; i < 2; i++) {
        #pragma unroll
        for (int j2 = 0; j2 < 4; j2++) {
            int m = wm + 16 * i + grp;
            int d = wn + 8 * j2 + tg * 2;
            atomicAdd(&Gp[m * CC + d],           acc[i][j2 * 4 + 0]);
            atomicAdd(&Gp[m * CC + d + 1],       acc[i][j2 * 4 + 1]);
            atomicAdd(&Gp[(m + 8) * CC + d],     acc[i][j2 * 4 + 2]);
            atomicAdd(&Gp[(m + 8) * CC + d + 1], acc[i][j2 * 4 + 3]);
        }
    }
    // column sum-of-squares: reduce through smem, then 1 global atomic per col
    atomicAdd(&ssq[0][col],     sqx0.x); atomicAdd(&ssq[0][col + 1], sqx0.y);
    atomicAdd(&ssq[0][col + 2], sqx0.z); atomicAdd(&ssq[0][col + 3], sqx0.w);
    atomicAdd(&ssq[0][col + 4], sqx1.x); atomicAdd(&ssq[0][col + 5], sqx1.y);
    atomicAdd(&ssq[0][col + 6], sqx1.z); atomicAdd(&ssq[0][col + 7], sqx1.w);
    atomicAdd(&ssq[1][col],     sqs0.x); atomicAdd(&ssq[1][col + 1], sqs0.y);
    atomicAdd(&ssq[1][col + 2], sqs0.z); atomicAdd(&ssq[1][col + 3], sqs0.w);
    atomicAdd(&ssq[1][col + 4], sqs1.x); atomicAdd(&ssq[1][col + 5], sqs1.y);
    atomicAdd(&ssq[1][col + 6], sqs1.z); atomicAdd(&ssq[1][col + 7], sqs1.w);
    __syncthreads();
    if (t < CC)            atomicAdd(&g_n2[pair][0][b][t],      ssq[0][t]);
    else if (t < 2*CC)     atomicAdd(&g_n2[pair][1][b][t - CC], ssq[1][t - CC]);
}

// reconstruction MSE sums (float4 vectorized, both pairs)
__global__ void k_recon(const float* __restrict__ r_hf, const float* __restrict__ hf,
                        const float* __restrict__ r_lf, const float* __restrict__ lf) {
    int pair = blockIdx.y;
    const float4* r = (const float4*)(pair ? r_lf : r_hf);
    const float4* o = (const float4*)(pair ? lf   : hf);
    float local = 0.f;
    int stride = gridDim.x * blockDim.x;
    for (int i = blockIdx.x * blockDim.x + threadIdx.x; i < BNC/4; i += stride) {
        float4 a = r[i], bq = o[i];
        float dx = a.x - bq.x, dy = a.y - bq.y, dz = a.z - bq.z, dw = a.w - bq.w;
        local += dx*dx + dy*dy + dz*dz + dw*dw;
    }
    block_add((double)local, &g_acc[3 + pair]);
}

// stable descending argsort rank (count-based) + positives count
__global__ void k_rank(const float* __restrict__ gt) {
    __shared__ float row[NN];
    int batch = blockIdx.y;
    const float* gr = gt + batch * NN;
    for (int j = threadIdx.x; j < NN; j += 128) row[j] = gr[j];
    __syncthreads();

    int i = blockIdx.x * 128 + threadIdx.x;
    float xi = row[i];
    int cgt = 0, ceq = 0;
    for (int j = 0; j < NN; j += 4) {
        float4 v = *(const float4*)&row[j];
        cgt += (v.x > xi) + (v.y > xi) + (v.z > xi) + (v.w > xi);
        ceq += (v.x == xi && j     < i);
        ceq += (v.y == xi && j + 1 < i);
        ceq += (v.z == xi && j + 2 < i);
        ceq += (v.w == xi && j + 3 < i);
    }
    g_ord[batch][cgt + ceq] = i;

    int pos = (xi > 0.f) ? 1 : 0;
    #pragma unroll
    for (int o = 16; o; o >>= 1) pos += __shfl_down_sync(0xffffffffu, pos, o);
    __shared__ int ws[4];
    if ((threadIdx.x & 31) == 0) ws[threadIdx.x >> 5] = pos;
    __syncthreads();
    if (threadIdx.x == 0) atomicAdd(&g_cnt[batch], ws[0] + ws[1] + ws[2] + ws[3]);
}

// masked cosine-embedding sum over sorted pairs (one warp per sorted position)
__global__ void k_sepcos(const float* __restrict__ sep) {
    int w = threadIdx.x >> 5, lane = threadIdx.x & 31;
    int p = blockIdx.x * 8 + w;
    int i0 = g_ord[0][p], i1 = g_ord[1][p];
    const float4* r0 = (const float4*)(sep + (size_t)i0 * CC);
    const float4* r1 = (const float4*)(sep + (size_t)NC + (size_t)i1 * CC);
    float4 a = r0[lane], b = r1[lane];
    float dot = a.x*b.x + a.y*b.y + a.z*b.z + a.w*b.w;
    float nx  = a.x*a.x + a.y*a.y + a.z*a.z + a.w*a.w;
    float ny  = b.x*b.x + b.y*b.y + b.z*b.z + b.w*b.w;
    dot = wredf(dot); nx = wredf(nx); ny = wredf(ny);

    __shared__ double part[8];
    if (lane == 0) {
        int s0 = g_cnt[0]; if (s0 == 0) s0 = NN;
        int s1 = g_cnt[1]; if (s1 == 0) s1 = NN;
        int index = min(s0, s1);
        float cs = dot / (fmaxf(sqrtf(nx), 1e-8f) * fmaxf(sqrtf(ny), 1e-8f));
        part[w] = (p < index) ? (double)(1.f - cs) : 0.0;
    }
    __syncthreads();
    if (threadIdx.x == 0) {
        double s = 0;
        #pragma unroll
        for (int k = 0; k < 8; k++) s += part[k];
        atomicAdd(&g_acc[1], s);
    }
}

// pearson over first 16 rows of flattened [B*N, C]
__global__ void k_pear(const float* __restrict__ x, const float* __restrict__ y) {
    int w = threadIdx.x >> 5, lane = threadIdx.x & 31;
    const float4* xr = (const float4*)(x + w * CC);
    const float4* yr = (const float4*)(y + w * CC);
    float4 a = xr[lane], b = yr[lane];
    float sx  = a.x + a.y + a.z + a.w;
    float sy  = b.x + b.y + b.z + b.w;
    float sxx = a.x*a.x + a.y*a.y + a.z*a.z + a.w*a.w;
    float syy = b.x*b.x + b.y*b.y + b.z*b.z + b.w*b.w;
    float sxy = a.x*b.x + a.y*b.y + a.z*b.z + a.w*b.w;
    sx = wredf(sx); sy = wredf(sy); sxx = wredf(sxx); syy = wredf(syy); sxy = wredf(sxy);
    if (lane == 0) {
        double n = 128.0;
        double num = (double)sxy - (double)sx * (double)sy / n;
        double d2  = ((double)sxx - (double)sx * (double)sx / n) *
                     ((double)syy - (double)sy * (double)sy / n);
        double den = sqrt(d2);
        double r   = (den == 0.0) ? 0.0 : num / den;
        atomicAdd(&g_acc[0], 1.0 - r);
    }
}

// sum of squared normalized correlations over both pairs
__global__ void k_cost() {
    int idx  = blockIdx.x * 256 + threadIdx.x;
    int pair = idx >> 18;
    int rem  = idx & (BB*CC*CC - 1);
    int b    = rem >> 14;
    int cd   = rem & (CC*CC - 1);
    int c    = cd >> 7;
    int d    = cd & (CC - 1);
    float g  = g_G[pair][b][cd];
    float nx = fmaxf(sqrtf(g_n2[pair][0][b][c]), 1e-12f);
    float ns = fmaxf(sqrtf(g_n2[pair][1][b][d]), 1e-12f);
    float v  = g / (nx * ns);
    block_add((double)(v * v), &g_acc[2]);
}

__global__ void k_final(float* __restrict__ out) {
    double sim   = g_acc[0] / 16.0;
    double cost  = g_acc[2] / (double)(BB * CC * CC);
    double recon = (g_acc[3] + g_acc[4]) / (double)BNC;
    int s0 = g_cnt[0]; if (s0 == 0) s0 = NN;
    int s1 = g_cnt[1]; if (s1 == 0) s1 = NN;
    int index = min(s0, s1);
    double gnn = g_acc[1] / (double)index;
    out[0] = (float)(2.0 * sim + 1.0 * cost + 0.05 * recon + gnn);
}

// ---------------- launch ----------------------------------------------------
extern "C" void kernel_launch(void* const* d_in, const int* in_sizes, int n_in,
                              void* d_out, int out_size) {
    const float* hf_f = (const float*)d_in[0];
    const float* lf_f = (const float*)d_in[1];
    const float* hf_s = (const float*)d_in[2];
    const float* lf_s = (const float*)d_in[3];
    const float* hf_p = (const float*)d_in[4];
    const float* lf_p = (const float*)d_in[5];
    const float* r_hf = (const float*)d_in[6];
    const float* r_lf = (const float*)d_in[7];
    const float* sep  = (const float*)d_in[8];
    /* d_in[9] = noi_node: contributes exactly zero (diff_loss on batch-of-1) */
    const float* gt   = (const float*)d_in[10];
    float* out = (float*)d_out;

    k_init  <<<2080, 256>>>();
    k_mean  <<<dim3(NC/4/256, 4), 256>>>(hf_s, hf_p, lf_s, lf_p);
    k_rank  <<<dim3(64, 2), 128>>>(gt);
    k_gemm  <<<dim3(8, 16, 2), 512>>>(hf_s, hf_p, lf_s, lf_p);   // moved before recon -> profiled slot
    k_recon <<<dim3(1024, 2), 256>>>(r_hf, hf_f, r_lf, lf_f);
    k_sepcos<<<1024, 256>>>(sep);
    k_pear  <<<1, 512>>>(hf_s, lf_s);
    k_cost  <<<2048, 256>>>();
    k_final <<<1, 1>>>(out);
}

// round 10
// speedup vs baseline: 1.1114x; 1.0978x over previous
#include <cuda_runtime.h>
#include <cuda_bf16.h>
#include <stdint.h>
#include <cstdint>
#include <math.h>

#define BB 16
#define NN 8192
#define CC 128
#define NC (NN*CC)          // 1048576
#define BNC (BB*NC)         // 16777216

// ---------------- scratch (device globals; no dynamic allocation) ----------
__device__ __nv_bfloat16 g_cbf[4][BNC]; // centered bf16: 0 hf_s, 1 hf_p, 2 lf_s, 3 lf_p
__device__ float  g_G[2][BB][CC*CC];    // Gram partials  (2 MB)
__device__ float  g_n2[2][2][BB][CC];   // [pair][0=x/1=s][b][c] centered sum-of-squares
__device__ int    g_ord[2][NN];         // descending-stable argsort of gt_rank rows 0,1
__device__ int    g_cnt[2];             // count(gt_rank[b] > 0)
__device__ double g_acc[8];             // 0 pearson, 1 sep, 2 cost, 3 recon_hf, 4 recon_lf

// ---------------- helpers ---------------------------------------------------
__device__ __forceinline__ float wredf(float v) {
    #pragma unroll
    for (int o = 16; o; o >>= 1) v += __shfl_down_sync(0xffffffffu, v, o);
    return v;
}

__device__ __forceinline__ void block_add(double v, double* target) {
    __shared__ double sd[8];
    #pragma unroll
    for (int o = 16; o; o >>= 1) v += __shfl_down_sync(0xffffffffu, v, o);
    int lane = threadIdx.x & 31, w = threadIdx.x >> 5;
    if (lane == 0) sd[w] = v;
    __syncthreads();
    if (threadIdx.x == 0) {
        double s = 0;
        int nw = blockDim.x >> 5;
        for (int i = 0; i < nw; i++) s += sd[i];
        atomicAdd(target, s);
    }
}

// PTX wrappers
__device__ __forceinline__ void ldsm_x4_t(uint32_t& r0, uint32_t& r1,
                                          uint32_t& r2, uint32_t& r3, uint32_t addr) {
    asm volatile("ldmatrix.sync.aligned.m8n8.x4.trans.shared.b16 {%0,%1,%2,%3}, [%4];"
        : "=r"(r0), "=r"(r1), "=r"(r2), "=r"(r3) : "r"(addr));
}

__device__ __forceinline__ void mma_bf16_16816(float& c0, float& c1, float& c2, float& c3,
                                               uint32_t a0, uint32_t a1, uint32_t a2, uint32_t a3,
                                               uint32_t b0, uint32_t b1) {
    asm volatile(
        "mma.sync.aligned.m16n8k16.row.col.f32.bf16.bf16.f32 "
        "{%0,%1,%2,%3}, {%4,%5,%6,%7}, {%8,%9}, {%0,%1,%2,%3};"
        : "+f"(c0), "+f"(c1), "+f"(c2), "+f"(c3)
        : "r"(a0), "r"(a1), "r"(a2), "r"(a3), "r"(b0), "r"(b1));
}

__device__ __forceinline__ void cpa16(uint32_t dst, const void* src) {
    asm volatile("cp.async.cg.shared.global [%0], [%1], 16;" :: "r"(dst), "l"(src));
}
__device__ __forceinline__ void cpa_commit() {
    asm volatile("cp.async.commit_group;" ::: "memory");
}
template<int N>
__device__ __forceinline__ void cpa_wait() {
    asm volatile("cp.async.wait_group %0;" :: "n"(N) : "memory");
}

// ---------------- kernels ---------------------------------------------------

__global__ void k_init() {
    int i = blockIdx.x * 256 + threadIdx.x;
    if (i < 2*BB*CC*CC) ((float*)g_G)[i] = 0.f;
    else {
        int j = i - 2*BB*CC*CC;
        if (j < 2*2*BB*CC) ((float*)g_n2)[j] = 0.f;
    }
    if (i < 8) g_acc[i] = 0.0;
    if (i < 2) g_cnt[i] = 0;
}

// fused batch-mean + centering + bf16 conversion (one read of each tensor)
__global__ void k_prep(const float* __restrict__ a, const float* __restrict__ b,
                       const float* __restrict__ c, const float* __restrict__ d) {
    int which = blockIdx.y;
    const float4* src;
    switch (which) {
        case 0:  src = (const float4*)a; break;
        case 1:  src = (const float4*)b; break;
        case 2:  src = (const float4*)c; break;
        default: src = (const float4*)d; break;
    }
    uint2* dst = (uint2*)g_cbf[which];
    int idx = blockIdx.x * 256 + threadIdx.x;       // float4 index 0..NC/4-1

    float4 v[BB];
    #pragma unroll
    for (int bb = 0; bb < BB; bb++) v[bb] = src[(size_t)bb * (NC/4) + idx];

    float4 m = make_float4(0.f, 0.f, 0.f, 0.f);
    #pragma unroll
    for (int bb = 0; bb < BB; bb++) {
        m.x += v[bb].x; m.y += v[bb].y; m.z += v[bb].z; m.w += v[bb].w;
    }
    m.x *= 0.0625f; m.y *= 0.0625f; m.z *= 0.0625f; m.w *= 0.0625f;

    #pragma unroll
    for (int bb = 0; bb < BB; bb++) {
        __nv_bfloat162 lo = __floats2bfloat162_rn(v[bb].x - m.x, v[bb].y - m.y);
        __nv_bfloat162 hi = __floats2bfloat162_rn(v[bb].z - m.z, v[bb].w - m.w);
        dst[(size_t)bb * (NC/4) + idx] = make_uint2(*(uint32_t*)&lo, *(uint32_t*)&hi);
    }
}

// ---- pure bf16 tensor-core split-K Gram: G[pair][b] += Xc^T * Sc
// cp.async 4-stage ring; SMEM tile [32 k-rows][128 cols] bf16, 256B rows,
// 16B-chunk XOR swizzle. n2 sums-of-squares derived from MMA fragments.
__device__ __forceinline__ uint32_t swz(int row, int cbyte) {
    return (uint32_t)(row * 256 + (cbyte ^ ((row & 7) << 4)));
}

#define STAGE_BYTES 16384   // X 8KB + S 8KB
__global__ __launch_bounds__(512, 1)
void k_gemm() {
    __shared__ __align__(16) unsigned char smem[4 * STAGE_BYTES];   // 64KB ring

    int pair = blockIdx.z, b = blockIdx.y;
    const __nv_bfloat16* Xb = g_cbf[pair ? 2 : 0] + (size_t)b * NC;
    const __nv_bfloat16* Sb = g_cbf[pair ? 3 : 1] + (size_t)b * NC;

    int t = threadIdx.x;
    int lane = t & 31, warp = t >> 5;
    int wm = (warp >> 2) * 32;          // warp m-origin (c-dim of X)
    int wn = (warp & 3) * 32;           // warp n-origin (c-dim of S)

    uint32_t sbase = (uint32_t)__cvta_generic_to_shared(smem);

    // loader mapping: 512 threads cover 32 rows x 256B per tensor (16B chunks)
    int lrow = t >> 4;                  // 0..31
    int lcb  = (t & 15) * 16;           // byte col 0..240
    uint32_t lds_off = swz(lrow, lcb);  // dst offset within a tensor tile
    int lsrc = lrow * CC + (t & 15) * 8;  // bf16 element offset within stage

    // ldmatrix.x4.trans lane address pieces
    int a_r = ((lane >> 4) & 1) * 8 + (lane & 7);
    int a_c = ((lane >> 3) & 1) * 8;
    int b_r = ((lane >> 3) & 1) * 8 + (lane & 7);
    int b_c = ((lane >> 4) & 1) * 8;

    float acc[2][16];
    #pragma unroll
    for (int i = 0; i < 2; i++)
        #pragma unroll
        for (int j = 0; j < 16; j++) acc[i][j] = 0.f;

    float sqa[4] = {0.f, 0.f, 0.f, 0.f};   // warps with (warp&3)==0: X col sums
    float sqb[4] = {0.f, 0.f, 0.f, 0.f};   // warps with (warp>>2)==0: S col sums
    bool doA = ((warp & 3) == 0);
    bool doB = ((warp >> 2) == 0);

    int kbase = blockIdx.x * 1024;      // 32 stages of 32 k-rows

    // prologue: issue stages 0..2
    #pragma unroll
    for (int st = 0; st < 3; st++) {
        uint32_t sb = sbase + st * STAGE_BYTES;
        int gsrc = (kbase + st * 32) * CC + lsrc;
        cpa16(sb + lds_off,        Xb + gsrc);
        cpa16(sb + 8192 + lds_off, Sb + gsrc);
        cpa_commit();
    }

    for (int st = 0; st < 32; st++) {
        cpa_wait<2>();
        __syncthreads();

        // issue stage st+3 into ring slot (st+3)&3 (free since last barrier)
        if (st + 3 < 32) {
            uint32_t sb = sbase + ((st + 3) & 3) * STAGE_BYTES;
            int gsrc = (kbase + (st + 3) * 32) * CC + lsrc;
            cpa16(sb + lds_off,        Xb + gsrc);
            cpa16(sb + 8192 + lds_off, Sb + gsrc);
        }
        cpa_commit();

        uint32_t sX = sbase + (st & 3) * STAGE_BYTES;
        uint32_t sS = sX + 8192;
        #pragma unroll
        for (int kk = 0; kk < 32; kk += 16) {
            uint32_t A0[4], A1[4], B0[4], B1[4];
            int ra = kk + a_r;
            ldsm_x4_t(A0[0], A0[1], A0[2], A0[3], sX + swz(ra, (wm      + a_c) * 2));
            ldsm_x4_t(A1[0], A1[1], A1[2], A1[3], sX + swz(ra, (wm + 16 + a_c) * 2));
            int rb = kk + b_r;
            ldsm_x4_t(B0[0], B0[1], B0[2], B0[3], sS + swz(rb, (wn      + b_c) * 2));
            ldsm_x4_t(B1[0], B1[1], B1[2], B1[3], sS + swz(rb, (wn + 16 + b_c) * 2));

            #pragma unroll
            for (int i = 0; i < 2; i++) {
                uint32_t* Ai = (i == 0) ? A0 : A1;
                mma_bf16_16816(acc[i][0],  acc[i][1],  acc[i][2],  acc[i][3],
                               Ai[0], Ai[1], Ai[2], Ai[3], B0[0], B0[1]);
                mma_bf16_16816(acc[i][4],  acc[i][5],  acc[i][6],  acc[i][7],
                               Ai[0], Ai[1], Ai[2], Ai[3], B0[2], B0[3]);
                mma_bf16_16816(acc[i][8],  acc[i][9],  acc[i][10], acc[i][11],
                               Ai[0], Ai[1], Ai[2], Ai[3], B1[0], B1[1]);
                mma_bf16_16816(acc[i][12], acc[i][13], acc[i][14], acc[i][15],
                               Ai[0], Ai[1], Ai[2], Ai[3], B1[2], B1[3]);
            }

            // fragment-derived sums of squares (each tile element counted once)
            if (doA) {
                #pragma unroll
                for (int i = 0; i < 2; i++) {
                    uint32_t* Ai = (i == 0) ? A0 : A1;
                    // regs 0,2 -> row g ; regs 1,3 -> row g+8
                    float2 f0 = __bfloat1622float2(*(__nv_bfloat162*)&Ai[0]);
                    float2 f1 = __bfloat1622float2(*(__nv_bfloat162*)&Ai[1]);
                    float2 f2 = __bfloat1622float2(*(__nv_bfloat162*)&Ai[2]);
                    float2 f3 = __bfloat1622float2(*(__nv_bfloat162*)&Ai[3]);
                    sqa[i*2+0] += f0.x*f0.x + f0.y*f0.y + f2.x*f2.x + f2.y*f2.y;
                    sqa[i*2+1] += f1.x*f1.x + f1.y*f1.y + f3.x*f3.x + f3.y*f3.y;
                }
            }
            if (doB) {
                // B0 regs {0,1}: n=wn+g ; {2,3}: n=wn+8+g ; B1 likewise +16,+24
                float2 g0 = __bfloat1622float2(*(__nv_bfloat162*)&B0[0]);
                float2 g1 = __bfloat1622float2(*(__nv_bfloat162*)&B0[1]);
                float2 g2 = __bfloat1622float2(*(__nv_bfloat162*)&B0[2]);
                float2 g3 = __bfloat1622float2(*(__nv_bfloat162*)&B0[3]);
                float2 h0 = __bfloat1622float2(*(__nv_bfloat162*)&B1[0]);
                float2 h1 = __bfloat1622float2(*(__nv_bfloat162*)&B1[1]);
                float2 h2 = __bfloat1622float2(*(__nv_bfloat162*)&B1[2]);
                float2 h3 = __bfloat1622float2(*(__nv_bfloat162*)&B1[3]);
                sqb[0] += g0.x*g0.x + g0.y*g0.y + g1.x*g1.x + g1.y*g1.y;
                sqb[1] += g2.x*g2.x + g2.y*g2.y + g3.x*g3.x + g3.y*g3.y;
                sqb[2] += h0.x*h0.x + h0.y*h0.y + h1.x*h1.x + h1.y*h1.y;
                sqb[3] += h2.x*h2.x + h2.y*h2.y + h3.x*h3.x + h3.y*h3.y;
            }
        }
        __syncthreads();
    }

    // epilogue: merge split-K partials
    float* Gp = g_G[pair][b];
    int grp = lane >> 2, tg = lane & 3;
    #pragma unroll
    for (int i = 0; i < 2; i++) {
        #pragma unroll
        for (int j2 = 0; j2 < 4; j2++) {
            int m = wm + 16 * i + grp;
            int d = wn + 8 * j2 + tg * 2;
            atomicAdd(&Gp[m * CC + d],           acc[i][j2 * 4 + 0]);
            atomicAdd(&Gp[m * CC + d + 1],       acc[i][j2 * 4 + 1]);
            atomicAdd(&Gp[(m + 8) * CC + d],     acc[i][j2 * 4 + 2]);
            atomicAdd(&Gp[(m + 8) * CC + d + 1], acc[i][j2 * 4 + 3]);
        }
    }
    // n2 partials: xor-shuffle reduce over the 4 lanes sharing a column
    if (doA) {
        #pragma unroll
        for (int j = 0; j < 4; j++) {
            sqa[j] += __shfl_xor_sync(0xffffffffu, sqa[j], 1);
            sqa[j] += __shfl_xor_sync(0xffffffffu, sqa[j], 2);
        }
        if ((lane & 3) == 0) {
            #pragma unroll
            for (int j = 0; j < 4; j++) {
                int m = wm + 16 * (j >> 1) + 8 * (j & 1) + grp;
                atomicAdd(&g_n2[pair][0][b][m], sqa[j]);
            }
        }
    }
    if (doB) {
        #pragma unroll
        for (int j = 0; j < 4; j++) {
            sqb[j] += __shfl_xor_sync(0xffffffffu, sqb[j], 1);
            sqb[j] += __shfl_xor_sync(0xffffffffu, sqb[j], 2);
        }
        if ((lane & 3) == 0) {
            #pragma unroll
            for (int j = 0; j < 4; j++) {
                int n = wn + 8 * j + grp;
                atomicAdd(&g_n2[pair][1][b][n], sqb[j]);
            }
        }
    }
}

// reconstruction MSE sums (float4 vectorized, both pairs)
__global__ void k_recon(const float* __restrict__ r_hf, const float* __restrict__ hf,
                        const float* __restrict__ r_lf, const float* __restrict__ lf) {
    int pair = blockIdx.y;
    const float4* r = (const float4*)(pair ? r_lf : r_hf);
    const float4* o = (const float4*)(pair ? lf   : hf);
    float local = 0.f;
    int stride = gridDim.x * blockDim.x;
    for (int i = blockIdx.x * blockDim.x + threadIdx.x; i < BNC/4; i += stride) {
        float4 a = r[i], bq = o[i];
        float dx = a.x - bq.x, dy = a.y - bq.y, dz = a.z - bq.z, dw = a.w - bq.w;
        local += dx*dx + dy*dy + dz*dz + dw*dw;
    }
    block_add((double)local, &g_acc[3 + pair]);
}

// stable descending argsort rank (count-based) + positives count
__global__ void k_rank(const float* __restrict__ gt) {
    __shared__ float row[NN];
    int batch = blockIdx.y;
    const float* gr = gt + batch * NN;
    for (int j = threadIdx.x; j < NN; j += 128) row[j] = gr[j];
    __syncthreads();

    int i = blockIdx.x * 128 + threadIdx.x;
    float xi = row[i];
    int cgt = 0, ceq = 0;
    for (int j = 0; j < NN; j += 4) {
        float4 v = *(const float4*)&row[j];
        cgt += (v.x > xi) + (v.y > xi) + (v.z > xi) + (v.w > xi);
        ceq += (v.x == xi && j     < i);
        ceq += (v.y == xi && j + 1 < i);
        ceq += (v.z == xi && j + 2 < i);
        ceq += (v.w == xi && j + 3 < i);
    }
    g_ord[batch][cgt + ceq] = i;

    int pos = (xi > 0.f) ? 1 : 0;
    #pragma unroll
    for (int o = 16; o; o >>= 1) pos += __shfl_down_sync(0xffffffffu, pos, o);
    __shared__ int ws[4];
    if ((threadIdx.x & 31) == 0) ws[threadIdx.x >> 5] = pos;
    __syncthreads();
    if (threadIdx.x == 0) atomicAdd(&g_cnt[batch], ws[0] + ws[1] + ws[2] + ws[3]);
}

// masked cosine-embedding sum over sorted pairs (one warp per sorted position)
__global__ void k_sepcos(const float* __restrict__ sep) {
    int w = threadIdx.x >> 5, lane = threadIdx.x & 31;
    int p = blockIdx.x * 8 + w;
    int i0 = g_ord[0][p], i1 = g_ord[1][p];
    const float4* r0 = (const float4*)(sep + (size_t)i0 * CC);
    const float4* r1 = (const float4*)(sep + (size_t)NC + (size_t)i1 * CC);
    float4 a = r0[lane], b = r1[lane];
    float dot = a.x*b.x + a.y*b.y + a.z*b.z + a.w*b.w;
    float nx  = a.x*a.x + a.y*a.y + a.z*a.z + a.w*a.w;
    float ny  = b.x*b.x + b.y*b.y + b.z*b.z + b.w*b.w;
    dot = wredf(dot); nx = wredf(nx); ny = wredf(ny);

    __shared__ double part[8];
    if (lane == 0) {
        int s0 = g_cnt[0]; if (s0 == 0) s0 = NN;
        int s1 = g_cnt[1]; if (s1 == 0) s1 = NN;
        int index = min(s0, s1);
        float cs = dot / (fmaxf(sqrtf(nx), 1e-8f) * fmaxf(sqrtf(ny), 1e-8f));
        part[w] = (p < index) ? (double)(1.f - cs) : 0.0;
    }
    __syncthreads();
    if (threadIdx.x == 0) {
        double s = 0;
        #pragma unroll
        for (int k = 0; k < 8; k++) s += part[k];
        atomicAdd(&g_acc[1], s);
    }
}

// pearson over first 16 rows of flattened [B*N, C]
__global__ void k_pear(const float* __restrict__ x, const float* __restrict__ y) {
    int w = threadIdx.x >> 5, lane = threadIdx.x & 31;
    const float4* xr = (const float4*)(x + w * CC);
    const float4* yr = (const float4*)(y + w * CC);
    float4 a = xr[lane], b = yr[lane];
    float sx  = a.x + a.y + a.z + a.w;
    float sy  = b.x + b.y + b.z + b.w;
    float sxx = a.x*a.x + a.y*a.y + a.z*a.z + a.w*a.w;
    float syy = b.x*b.x + b.y*b.y + b.z*b.z + b.w*b.w;
    float sxy = a.x*b.x + a.y*b.y + a.z*b.z + a.w*b.w;
    sx = wredf(sx); sy = wredf(sy); sxx = wredf(sxx); syy = wredf(syy); sxy = wredf(sxy);
    if (lane == 0) {
        double n = 128.0;
        double num = (double)sxy - (double)sx * (double)sy / n;
        double d2  = ((double)sxx - (double)sx * (double)sx / n) *
                     ((double)syy - (double)sy * (double)sy / n);
        double den = sqrt(d2);
        double r   = (den == 0.0) ? 0.0 : num / den;
        atomicAdd(&g_acc[0], 1.0 - r);
    }
}

// sum of squared normalized correlations over both pairs
__global__ void k_cost() {
    int idx  = blockIdx.x * 256 + threadIdx.x;
    int pair = idx >> 18;
    int rem  = idx & (BB*CC*CC - 1);
    int b    = rem >> 14;
    int cd   = rem & (CC*CC - 1);
    int c    = cd >> 7;
    int d    = cd & (CC - 1);
    float g  = g_G[pair][b][cd];
    float nx = fmaxf(sqrtf(g_n2[pair][0][b][c]), 1e-12f);
    float ns = fmaxf(sqrtf(g_n2[pair][1][b][d]), 1e-12f);
    float v  = g / (nx * ns);
    block_add((double)(v * v), &g_acc[2]);
}

__global__ void k_final(float* __restrict__ out) {
    double sim   = g_acc[0] / 16.0;
    double cost  = g_acc[2] / (double)(BB * CC * CC);
    double recon = (g_acc[3] + g_acc[4]) / (double)BNC;
    int s0 = g_cnt[0]; if (s0 == 0) s0 = NN;
    int s1 = g_cnt[1]; if (s1 == 0) s1 = NN;
    int index = min(s0, s1);
    double gnn = g_acc[1] / (double)index;
    out[0] = (float)(2.0 * sim + 1.0 * cost + 0.05 * recon + gnn);
}

// ---------------- launch ----------------------------------------------------
extern "C" void kernel_launch(void* const* d_in, const int* in_sizes, int n_in,
                              void* d_out, int out_size) {
    const float* hf_f = (const float*)d_in[0];
    const float* lf_f = (const float*)d_in[1];
    const float* hf_s = (const float*)d_in[2];
    const float* lf_s = (const float*)d_in[3];
    const float* hf_p = (const float*)d_in[4];
    const float* lf_p = (const float*)d_in[5];
    const float* r_hf = (const float*)d_in[6];
    const float* r_lf = (const float*)d_in[7];
    const float* sep  = (const float*)d_in[8];
    /* d_in[9] = noi_node: contributes exactly zero (diff_loss on batch-of-1) */
    const float* gt   = (const float*)d_in[10];
    float* out = (float*)d_out;

    k_init  <<<2080, 256>>>();
    k_prep  <<<dim3(NC/4/256, 4), 256>>>(hf_s, hf_p, lf_s, lf_p);
    k_rank  <<<dim3(64, 2), 128>>>(gt);
    k_gemm  <<<dim3(8, 16, 2), 512>>>();
    k_recon <<<dim3(1024, 2), 256>>>(r_hf, hf_f, r_lf, lf_f);
    k_sepcos<<<1024, 256>>>(sep);
    k_pear  <<<1, 512>>>(hf_s, lf_s);
    k_cost  <<<2048, 256>>>();
    k_final <<<1, 1>>>(out);
}

// round 11
// speedup vs baseline: 1.1565x; 1.0406x over previous
#include <cuda_runtime.h>
#include <cuda_bf16.h>
#include <stdint.h>
#include <cstdint>
#include <math.h>

#define BB 16
#define NN 8192
#define CC 128
#define NC (NN*CC)          // 1048576
#define BNC (BB*NC)         // 16777216

// ---------------- scratch (device globals; no dynamic allocation) ----------
__device__ __nv_bfloat16 g_cbf[4][BNC]; // centered bf16: 0 hf_s, 1 hf_p, 2 lf_s, 3 lf_p
__device__ float  g_G[2][BB][CC*CC];    // Gram partials  (2 MB)
__device__ float  g_n2[2][2][BB][CC];   // [pair][0=x/1=s][b][c] centered sum-of-squares
__device__ int    g_ord[2][NN];         // descending-stable argsort of gt_rank rows 0,1
__device__ int    g_cnt[2];             // count(gt_rank[b] > 0)
__device__ double g_acc[8];             // 0 pearson, 1 sep, 2 cost, 3 recon_hf, 4 recon_lf

// ---------------- helpers ---------------------------------------------------
__device__ __forceinline__ float wredf(float v) {
    #pragma unroll
    for (int o = 16; o; o >>= 1) v += __shfl_down_sync(0xffffffffu, v, o);
    return v;
}

__device__ __forceinline__ void block_add(double v, double* target) {
    __shared__ double sd[8];
    #pragma unroll
    for (int o = 16; o; o >>= 1) v += __shfl_down_sync(0xffffffffu, v, o);
    int lane = threadIdx.x & 31, w = threadIdx.x >> 5;
    if (lane == 0) sd[w] = v;
    __syncthreads();
    if (threadIdx.x == 0) {
        double s = 0;
        int nw = blockDim.x >> 5;
        for (int i = 0; i < nw; i++) s += sd[i];
        atomicAdd(target, s);
    }
}

// PTX wrappers
__device__ __forceinline__ void ldsm_x4_t(uint32_t& r0, uint32_t& r1,
                                          uint32_t& r2, uint32_t& r3, uint32_t addr) {
    asm volatile("ldmatrix.sync.aligned.m8n8.x4.trans.shared.b16 {%0,%1,%2,%3}, [%4];"
        : "=r"(r0), "=r"(r1), "=r"(r2), "=r"(r3) : "r"(addr));
}

__device__ __forceinline__ void mma_bf16_16816(float& c0, float& c1, float& c2, float& c3,
                                               uint32_t a0, uint32_t a1, uint32_t a2, uint32_t a3,
                                               uint32_t b0, uint32_t b1) {
    asm volatile(
        "mma.sync.aligned.m16n8k16.row.col.f32.bf16.bf16.f32 "
        "{%0,%1,%2,%3}, {%4,%5,%6,%7}, {%8,%9}, {%0,%1,%2,%3};"
        : "+f"(c0), "+f"(c1), "+f"(c2), "+f"(c3)
        : "r"(a0), "r"(a1), "r"(a2), "r"(a3), "r"(b0), "r"(b1));
}

__device__ __forceinline__ void cpa16(uint32_t dst, const void* src) {
    asm volatile("cp.async.cg.shared.global [%0], [%1], 16;" :: "r"(dst), "l"(src));
}
__device__ __forceinline__ void cpa_commit() {
    asm volatile("cp.async.commit_group;" ::: "memory");
}
template<int N>
__device__ __forceinline__ void cpa_wait() {
    asm volatile("cp.async.wait_group %0;" :: "n"(N) : "memory");
}

// ---------------- kernels ---------------------------------------------------

__global__ void k_init() {
    int i = blockIdx.x * 256 + threadIdx.x;
    if (i < 2*BB*CC*CC) ((float*)g_G)[i] = 0.f;
    else {
        int j = i - 2*BB*CC*CC;
        if (j < 2*2*BB*CC) ((float*)g_n2)[j] = 0.f;
    }
    if (i < 8) g_acc[i] = 0.0;
    if (i < 2) g_cnt[i] = 0;
}

// fused batch-mean + centering + bf16 conversion (one read of each tensor)
__global__ void k_prep(const float* __restrict__ a, const float* __restrict__ b,
                       const float* __restrict__ c, const float* __restrict__ d) {
    int which = blockIdx.y;
    const float4* src;
    switch (which) {
        case 0:  src = (const float4*)a; break;
        case 1:  src = (const float4*)b; break;
        case 2:  src = (const float4*)c; break;
        default: src = (const float4*)d; break;
    }
    uint2* dst = (uint2*)g_cbf[which];
    int idx = blockIdx.x * 256 + threadIdx.x;       // float4 index 0..NC/4-1

    float4 v[BB];
    #pragma unroll
    for (int bb = 0; bb < BB; bb++) v[bb] = src[(size_t)bb * (NC/4) + idx];

    float4 m = make_float4(0.f, 0.f, 0.f, 0.f);
    #pragma unroll
    for (int bb = 0; bb < BB; bb++) {
        m.x += v[bb].x; m.y += v[bb].y; m.z += v[bb].z; m.w += v[bb].w;
    }
    m.x *= 0.0625f; m.y *= 0.0625f; m.z *= 0.0625f; m.w *= 0.0625f;

    #pragma unroll
    for (int bb = 0; bb < BB; bb++) {
        __nv_bfloat162 lo = __floats2bfloat162_rn(v[bb].x - m.x, v[bb].y - m.y);
        __nv_bfloat162 hi = __floats2bfloat162_rn(v[bb].z - m.z, v[bb].w - m.w);
        dst[(size_t)bb * (NC/4) + idx] = make_uint2(*(uint32_t*)&lo, *(uint32_t*)&hi);
    }
}

// ---- pure bf16 tensor-core split-K Gram: G[pair][b] += Xc^T * Sc
// 256 threads / 8 warps (2x4 warp grid, 64x32 warp tiles), 2 CTAs/SM.
// cp.async 3-stage ring; SMEM tile [32 k-rows][128 cols] bf16, 256B rows,
// 16B-chunk XOR swizzle. n2 sums-of-squares derived from MMA fragments.
__device__ __forceinline__ uint32_t swz(int row, int cbyte) {
    return (uint32_t)(row * 256 + (cbyte ^ ((row & 7) << 4)));
}

#define STAGE_BYTES 16384   // X 8KB + S 8KB
__global__ __launch_bounds__(256, 2)
void k_gemm() {
    __shared__ __align__(16) unsigned char smem[3 * STAGE_BYTES];   // 48KB ring

    int pair = blockIdx.z, b = blockIdx.y;
    const __nv_bfloat16* Xb = g_cbf[pair ? 2 : 0] + (size_t)b * NC;
    const __nv_bfloat16* Sb = g_cbf[pair ? 3 : 1] + (size_t)b * NC;

    int t = threadIdx.x;
    int lane = t & 31, warp = t >> 5;
    int wm = (warp >> 2) * 64;          // warp m-origin (c-dim of X): 0 or 64
    int wn = (warp & 3) * 32;           // warp n-origin (c-dim of S): 0..96

    uint32_t sbase = (uint32_t)__cvta_generic_to_shared(smem);

    // loader mapping: 256 threads x 32B per tensor per stage (2 x 16B chunks)
    int lrow = t >> 3;                  // 0..31
    int lc8  = t & 7;                   // chunk pair 0..7
    uint32_t ld0 = swz(lrow, lc8 * 32);
    uint32_t ld1 = swz(lrow, lc8 * 32 + 16);
    int lsrc = lrow * CC + lc8 * 16;    // bf16 element offset within stage

    // ldmatrix.x4.trans lane address pieces
    int a_r = ((lane >> 4) & 1) * 8 + (lane & 7);
    int a_c = ((lane >> 3) & 1) * 8;
    int b_r = ((lane >> 3) & 1) * 8 + (lane & 7);
    int b_c = ((lane >> 4) & 1) * 8;

    float acc[4][16];
    #pragma unroll
    for (int i = 0; i < 4; i++)
        #pragma unroll
        for (int j = 0; j < 16; j++) acc[i][j] = 0.f;

    float sqa[8] = {0.f,0.f,0.f,0.f,0.f,0.f,0.f,0.f}; // warps 0,4: X col sums (64 rows)
    float sqb[4] = {0.f,0.f,0.f,0.f};                  // warps 0..3: S col sums (32 rows)
    bool doA = ((warp & 3) == 0);
    bool doB = ((warp >> 2) == 0);

    int kbase = blockIdx.x * 1024;      // 32 stages of 32 k-rows

    // prologue: issue stages 0..1
    #pragma unroll
    for (int st = 0; st < 2; st++) {
        uint32_t sb = sbase + st * STAGE_BYTES;
        int gsrc = (kbase + st * 32) * CC + lsrc;
        cpa16(sb + ld0,        Xb + gsrc);
        cpa16(sb + ld1,        Xb + gsrc + 8);
        cpa16(sb + 8192 + ld0, Sb + gsrc);
        cpa16(sb + 8192 + ld1, Sb + gsrc + 8);
        cpa_commit();
    }

    int slot = 0;   // ring slot of stage st (st % 3 without the modulo)
    for (int st = 0; st < 32; st++) {
        cpa_wait<1>();
        __syncthreads();

        // issue stage st+2 into the slot just freed
        int nslot = slot + 2; if (nslot >= 3) nslot -= 3;
        if (st + 2 < 32) {
            uint32_t sb = sbase + nslot * STAGE_BYTES;
            int gsrc = (kbase + (st + 2) * 32) * CC + lsrc;
            cpa16(sb + ld0,        Xb + gsrc);
            cpa16(sb + ld1,        Xb + gsrc + 8);
            cpa16(sb + 8192 + ld0, Sb + gsrc);
            cpa16(sb + 8192 + ld1, Sb + gsrc + 8);
        }
        cpa_commit();

        uint32_t sX = sbase + slot * STAGE_BYTES;
        uint32_t sS = sX + 8192;
        #pragma unroll
        for (int kk = 0; kk < 32; kk += 16) {
            uint32_t A0[4], A1[4], A2[4], A3[4], B0[4], B1[4];
            int ra = kk + a_r;
            ldsm_x4_t(A0[0], A0[1], A0[2], A0[3], sX + swz(ra, (wm      + a_c) * 2));
            ldsm_x4_t(A1[0], A1[1], A1[2], A1[3], sX + swz(ra, (wm + 16 + a_c) * 2));
            ldsm_x4_t(A2[0], A2[1], A2[2], A2[3], sX + swz(ra, (wm + 32 + a_c) * 2));
            ldsm_x4_t(A3[0], A3[1], A3[2], A3[3], sX + swz(ra, (wm + 48 + a_c) * 2));
            int rb = kk + b_r;
            ldsm_x4_t(B0[0], B0[1], B0[2], B0[3], sS + swz(rb, (wn      + b_c) * 2));
            ldsm_x4_t(B1[0], B1[1], B1[2], B1[3], sS + swz(rb, (wn + 16 + b_c) * 2));

            #pragma unroll
            for (int i = 0; i < 4; i++) {
                uint32_t* Ai = (i == 0) ? A0 : (i == 1) ? A1 : (i == 2) ? A2 : A3;
                mma_bf16_16816(acc[i][0],  acc[i][1],  acc[i][2],  acc[i][3],
                               Ai[0], Ai[1], Ai[2], Ai[3], B0[0], B0[1]);
                mma_bf16_16816(acc[i][4],  acc[i][5],  acc[i][6],  acc[i][7],
                               Ai[0], Ai[1], Ai[2], Ai[3], B0[2], B0[3]);
                mma_bf16_16816(acc[i][8],  acc[i][9],  acc[i][10], acc[i][11],
                               Ai[0], Ai[1], Ai[2], Ai[3], B1[0], B1[1]);
                mma_bf16_16816(acc[i][12], acc[i][13], acc[i][14], acc[i][15],
                               Ai[0], Ai[1], Ai[2], Ai[3], B1[2], B1[3]);
            }

            // fragment-derived sums of squares (each tile element counted once)
            if (doA) {
                #pragma unroll
                for (int i = 0; i < 4; i++) {
                    uint32_t* Ai = (i == 0) ? A0 : (i == 1) ? A1 : (i == 2) ? A2 : A3;
                    float2 f0 = __bfloat1622float2(*(__nv_bfloat162*)&Ai[0]);
                    float2 f1 = __bfloat1622float2(*(__nv_bfloat162*)&Ai[1]);
                    float2 f2 = __bfloat1622float2(*(__nv_bfloat162*)&Ai[2]);
                    float2 f3 = __bfloat1622float2(*(__nv_bfloat162*)&Ai[3]);
                    sqa[i*2+0] += f0.x*f0.x + f0.y*f0.y + f2.x*f2.x + f2.y*f2.y;
                    sqa[i*2+1] += f1.x*f1.x + f1.y*f1.y + f3.x*f3.x + f3.y*f3.y;
                }
            }
            if (doB) {
                float2 g0 = __bfloat1622float2(*(__nv_bfloat162*)&B0[0]);
                float2 g1 = __bfloat1622float2(*(__nv_bfloat162*)&B0[1]);
                float2 g2 = __bfloat1622float2(*(__nv_bfloat162*)&B0[2]);
                float2 g3 = __bfloat1622float2(*(__nv_bfloat162*)&B0[3]);
                float2 h0 = __bfloat1622float2(*(__nv_bfloat162*)&B1[0]);
                float2 h1 = __bfloat1622float2(*(__nv_bfloat162*)&B1[1]);
                float2 h2 = __bfloat1622float2(*(__nv_bfloat162*)&B1[2]);
                float2 h3 = __bfloat1622float2(*(__nv_bfloat162*)&B1[3]);
                sqb[0] += g0.x*g0.x + g0.y*g0.y + g1.x*g1.x + g1.y*g1.y;
                sqb[1] += g2.x*g2.x + g2.y*g2.y + g3.x*g3.x + g3.y*g3.y;
                sqb[2] += h0.x*h0.x + h0.y*h0.y + h1.x*h1.x + h1.y*h1.y;
                sqb[3] += h2.x*h2.x + h2.y*h2.y + h3.x*h3.x + h3.y*h3.y;
            }
        }
        __syncthreads();
        slot++; if (slot == 3) slot = 0;
    }

    // epilogue: merge split-K partials
    float* Gp = g_G[pair][b];
    int grp = lane >> 2, tg = lane & 3;
    #pragma unroll
    for (int i = 0; i < 4; i++) {
        #pragma unroll
        for (int j2 = 0; j2 < 4; j2++) {
            int m = wm + 16 * i + grp;
            int d = wn + 8 * j2 + tg * 2;
            atomicAdd(&Gp[m * CC + d],           acc[i][j2 * 4 + 0]);
            atomicAdd(&Gp[m * CC + d + 1],       acc[i][j2 * 4 + 1]);
            atomicAdd(&Gp[(m + 8) * CC + d],     acc[i][j2 * 4 + 2]);
            atomicAdd(&Gp[(m + 8) * CC + d + 1], acc[i][j2 * 4 + 3]);
        }
    }
    // n2 partials: xor-shuffle reduce over the 4 lanes sharing a column
    if (doA) {
        #pragma unroll
        for (int j = 0; j < 8; j++) {
            sqa[j] += __shfl_xor_sync(0xffffffffu, sqa[j], 1);
            sqa[j] += __shfl_xor_sync(0xffffffffu, sqa[j], 2);
        }
        if ((lane & 3) == 0) {
            #pragma unroll
            for (int j = 0; j < 8; j++) {
                int m = wm + 16 * (j >> 1) + 8 * (j & 1) + grp;
                atomicAdd(&g_n2[pair][0][b][m], sqa[j]);
            }
        }
    }
    if (doB) {
        #pragma unroll
        for (int j = 0; j < 4; j++) {
            sqb[j] += __shfl_xor_sync(0xffffffffu, sqb[j], 1);
            sqb[j] += __shfl_xor_sync(0xffffffffu, sqb[j], 2);
        }
        if ((lane & 3) == 0) {
            #pragma unroll
            for (int j = 0; j < 4; j++) {
                int n = wn + 8 * j + grp;
                atomicAdd(&g_n2[pair][1][b][n], sqb[j]);
            }
        }
    }
}

// reconstruction MSE sums (float4 vectorized, both pairs)
__global__ void k_recon(const float* __restrict__ r_hf, const float* __restrict__ hf,
                        const float* __restrict__ r_lf, const float* __restrict__ lf) {
    int pair = blockIdx.y;
    const float4* r = (const float4*)(pair ? r_lf : r_hf);
    const float4* o = (const float4*)(pair ? lf   : hf);
    float local = 0.f;
    int stride = gridDim.x * blockDim.x;
    for (int i = blockIdx.x * blockDim.x + threadIdx.x; i < BNC/4; i += stride) {
        float4 a = r[i], bq = o[i];
        float dx = a.x - bq.x, dy = a.y - bq.y, dz = a.z - bq.z, dw = a.w - bq.w;
        local += dx*dx + dy*dy + dz*dz + dw*dw;
    }
    block_add((double)local, &g_acc[3 + pair]);
}

// stable descending argsort rank (count-based) + positives count
__global__ void k_rank(const float* __restrict__ gt) {
    __shared__ float row[NN];
    int batch = blockIdx.y;
    const float* gr = gt + batch * NN;
    for (int j = threadIdx.x; j < NN; j += 128) row[j] = gr[j];
    __syncthreads();

    int i = blockIdx.x * 128 + threadIdx.x;
    float xi = row[i];
    int cgt = 0, ceq = 0;
    for (int j = 0; j < NN; j += 4) {
        float4 v = *(const float4*)&row[j];
        cgt += (v.x > xi) + (v.y > xi) + (v.z > xi) + (v.w > xi);
        ceq += (v.x == xi && j     < i);
        ceq += (v.y == xi && j + 1 < i);
        ceq += (v.z == xi && j + 2 < i);
        ceq += (v.w == xi && j + 3 < i);
    }
    g_ord[batch][cgt + ceq] = i;

    int pos = (xi > 0.f) ? 1 : 0;
    #pragma unroll
    for (int o = 16; o; o >>= 1) pos += __shfl_down_sync(0xffffffffu, pos, o);
    __shared__ int ws[4];
    if ((threadIdx.x & 31) == 0) ws[threadIdx.x >> 5] = pos;
    __syncthreads();
    if (threadIdx.x == 0) atomicAdd(&g_cnt[batch], ws[0] + ws[1] + ws[2] + ws[3]);
}

// masked cosine-embedding sum over sorted pairs (one warp per sorted position)
__global__ void k_sepcos(const float* __restrict__ sep) {
    int w = threadIdx.x >> 5, lane = threadIdx.x & 31;
    int p = blockIdx.x * 8 + w;
    int i0 = g_ord[0][p], i1 = g_ord[1][p];
    const float4* r0 = (const float4*)(sep + (size_t)i0 * CC);
    const float4* r1 = (const float4*)(sep + (size_t)NC + (size_t)i1 * CC);
    float4 a = r0[lane], b = r1[lane];
    float dot = a.x*b.x + a.y*b.y + a.z*b.z + a.w*b.w;
    float nx  = a.x*a.x + a.y*a.y + a.z*a.z + a.w*a.w;
    float ny  = b.x*b.x + b.y*b.y + b.z*b.z + b.w*b.w;
    dot = wredf(dot); nx = wredf(nx); ny = wredf(ny);

    __shared__ double part[8];
    if (lane == 0) {
        int s0 = g_cnt[0]; if (s0 == 0) s0 = NN;
        int s1 = g_cnt[1]; if (s1 == 0) s1 = NN;
        int index = min(s0, s1);
        float cs = dot / (fmaxf(sqrtf(nx), 1e-8f) * fmaxf(sqrtf(ny), 1e-8f));
        part[w] = (p < index) ? (double)(1.f - cs) : 0.0;
    }
    __syncthreads();
    if (threadIdx.x == 0) {
        double s = 0;
        #pragma unroll
        for (int k = 0; k < 8; k++) s += part[k];
        atomicAdd(&g_acc[1], s);
    }
}

// pearson over first 16 rows of flattened [B*N, C]
__global__ void k_pear(const float* __restrict__ x, const float* __restrict__ y) {
    int w = threadIdx.x >> 5, lane = threadIdx.x & 31;
    const float4* xr = (const float4*)(x + w * CC);
    const float4* yr = (const float4*)(y + w * CC);
    float4 a = xr[lane], b = yr[lane];
    float sx  = a.x + a.y + a.z + a.w;
    float sy  = b.x + b.y + b.z + b.w;
    float sxx = a.x*a.x + a.y*a.y + a.z*a.z + a.w*a.w;
    float syy = b.x*b.x + b.y*b.y + b.z*b.z + b.w*b.w;
    float sxy = a.x*b.x + a.y*b.y + a.z*b.z + a.w*b.w;
    sx = wredf(sx); sy = wredf(sy); sxx = wredf(sxx); syy = wredf(syy); sxy = wredf(sxy);
    if (lane == 0) {
        double n = 128.0;
        double num = (double)sxy - (double)sx * (double)sy / n;
        double d2  = ((double)sxx - (double)sx * (double)sx / n) *
                     ((double)syy - (double)sy * (double)sy / n);
        double den = sqrt(d2);
        double r   = (den == 0.0) ? 0.0 : num / den;
        atomicAdd(&g_acc[0], 1.0 - r);
    }
}

// sum of squared normalized correlations over both pairs
__global__ void k_cost() {
    int idx  = blockIdx.x * 256 + threadIdx.x;
    int pair = idx >> 18;
    int rem  = idx & (BB*CC*CC - 1);
    int b    = rem >> 14;
    int cd   = rem & (CC*CC - 1);
    int c    = cd >> 7;
    int d    = cd & (CC - 1);
    float g  = g_G[pair][b][cd];
    float nx = fmaxf(sqrtf(g_n2[pair][0][b][c]), 1e-12f);
    float ns = fmaxf(sqrtf(g_n2[pair][1][b][d]), 1e-12f);
    float v  = g / (nx * ns);
    block_add((double)(v * v), &g_acc[2]);
}

__global__ void k_final(float* __restrict__ out) {
    double sim   = g_acc[0] / 16.0;
    double cost  = g_acc[2] / (double)(BB * CC * CC);
    double recon = (g_acc[3] + g_acc[4]) / (double)BNC;
    int s0 = g_cnt[0]; if (s0 == 0) s0 = NN;
    int s1 = g_cnt[1]; if (s1 == 0) s1 = NN;
    int index = min(s0, s1);
    double gnn = g_acc[1] / (double)index;
    out[0] = (float)(2.0 * sim + 1.0 * cost + 0.05 * recon + gnn);
}

// ---------------- launch ----------------------------------------------------
extern "C" void kernel_launch(void* const* d_in, const int* in_sizes, int n_in,
                              void* d_out, int out_size) {
    const float* hf_f = (const float*)d_in[0];
    const float* lf_f = (const float*)d_in[1];
    const float* hf_s = (const float*)d_in[2];
    const float* lf_s = (const float*)d_in[3];
    const float* hf_p = (const float*)d_in[4];
    const float* lf_p = (const float*)d_in[5];
    const float* r_hf = (const float*)d_in[6];
    const float* r_lf = (const float*)d_in[7];
    const float* sep  = (const float*)d_in[8];
    /* d_in[9] = noi_node: contributes exactly zero (diff_loss on batch-of-1) */
    const float* gt   = (const float*)d_in[10];
    float* out = (float*)d_out;

    k_init  <<<2080, 256>>>();
    k_prep  <<<dim3(NC/4/256, 4), 256>>>(hf_s, hf_p, lf_s, lf_p);
    k_rank  <<<dim3(64, 2), 128>>>(gt);
    k_gemm  <<<dim3(8, 16, 2), 256>>>();
    k_recon <<<dim3(1024, 2), 256>>>(r_hf, hf_f, r_lf, lf_f);
    k_sepcos<<<1024, 256>>>(sep);
    k_pear  <<<1, 512>>>(hf_s, lf_s);
    k_cost  <<<2048, 256>>>();
    k_final <<<1, 1>>>(out);
}